// round 14
// baseline (speedup 1.0000x reference)
#include <cuda_runtime.h>
#include <cstdint>
#include <cstddef>

#define SEQT 2048
#define NTAG 12
#define STARTT 10
#define STOPT 11
#define NEGV -10000.0f

// ---------------- scratch (device globals; no allocation) ----------------
__device__ float g_pre[2][SEQT][1024];      // 16 MB: input projections (i,f,g,o rows)
__device__ float g_hs[SEQT][512];           // 4 MB: [hf | hb] per timestep
__device__ float g_feats[SEQT][NTAG];
__device__ float g_P[SEQT / 32][NTAG][NTAG];

// ---------------- helpers ----------------
__device__ __forceinline__ unsigned long long fma2(unsigned long long a, unsigned long long b,
                                                   unsigned long long c) {
    unsigned long long d;
    asm("fma.rn.f32x2 %0, %1, %2, %3;" : "=l"(d) : "l"(a), "l"(b), "l"(c));
    return d;
}
__device__ __forceinline__ unsigned long long add2(unsigned long long a, unsigned long long b) {
    unsigned long long d;
    asm("add.rn.f32x2 %0, %1, %2;" : "=l"(d) : "l"(a), "l"(b));
    return d;
}
__device__ __forceinline__ float2 unpack2(unsigned long long u) {
    float2 f;
    asm("mov.b64 {%0, %1}, %2;" : "=f"(f.x), "=f"(f.y) : "l"(u));
    return f;
}
__device__ __forceinline__ unsigned long long pack2f(float lo, float hi) {
    unsigned long long u;
    asm("mov.b64 %0, {%1, %2};" : "=l"(u) : "f"(lo), "f"(hi));
    return u;
}
__device__ __forceinline__ unsigned smem_u32(const void* p) {
    return (unsigned)__cvta_generic_to_shared(p);
}
__device__ __forceinline__ unsigned ctarank() {
    unsigned r;
    asm("mov.u32 %0, %%cluster_ctarank;" : "=r"(r));
    return r;
}
__device__ __forceinline__ unsigned mapa_u32(unsigned local_addr, unsigned rank) {
    unsigned r;
    asm("mapa.shared::cluster.u32 %0, %1, %2;" : "=r"(r) : "r"(local_addr), "r"(rank));
    return r;
}
// HW tanh (MUFU.TANH, single ~16cyc MUFU vs 2 dependent MUFUs for exp-based)
__device__ __forceinline__ float tanh_hw(float x) {
    float y;
    asm("tanh.approx.f32 %0, %1;" : "=f"(y) : "f"(x));
    return y;
}
__device__ __forceinline__ float sig_hw(float x) {
    return fmaf(0.5f, tanh_hw(0.5f * x), 0.5f);
}

#define CLUSTER_SYNC_()                                                \
    do {                                                               \
        asm volatile("barrier.cluster.arrive.aligned;" ::: "memory");  \
        asm volatile("barrier.cluster.wait.aligned;" ::: "memory");    \
    } while (0)

// cluster-scope acquire parity wait on a local-CTA mbarrier (proven R2/R7-R10)
__device__ __forceinline__ void mbar_wait_cluster(unsigned addr, int phase) {
    unsigned done;
    asm volatile(
        "{\n\t.reg .pred p;\n\t"
        "mbarrier.try_wait.parity.acquire.cluster.shared::cta.b64 p, [%1], %2;\n\t"
        "selp.b32 %0, 1, 0, p;\n\t}"
        : "=r"(done) : "r"(addr), "r"((unsigned)phase) : "memory");
    if (!done) {
        asm volatile(
            "{\n\t.reg .pred P1;\n\t"
            "WL_%=:\n\t"
            "mbarrier.try_wait.parity.acquire.cluster.shared::cta.b64 P1, [%0], %1, 0x989680;\n\t"
            "@P1 bra.uni WD_%=;\n\t"
            "bra.uni WL_%=;\n\t"
            "WD_%=:\n\t}"
            :: "r"(addr), "r"((unsigned)phase) : "memory");
    }
}

// DSMEM bulk copy: local smem -> peer smem, completion tx on the PEER's mbarrier.
__device__ __forceinline__ void bulk_dsmem(unsigned dst_cluster, unsigned src_cta,
                                           unsigned bytes, unsigned mbar_cluster) {
    asm volatile(
        "cp.async.bulk.shared::cluster.shared::cta.mbarrier::complete_tx::bytes "
        "[%0], [%1], %2, [%3];"
        :: "r"(dst_cluster), "r"(src_cta), "r"(bytes), "r"(mbar_cluster)
        : "memory");
}

// ---------------- kernel A: embedding gather + input projection ----------------
__global__ void __launch_bounds__(256) proj_kernel(
    const int* __restrict__ sent, const float* __restrict__ embed,
    const float* __restrict__ Wf, const float* __restrict__ bihf, const float* __restrict__ bhhf,
    const float* __restrict__ Wb, const float* __restrict__ bihb, const float* __restrict__ bhhb) {
    __shared__ __align__(16) float xs[8][256];
    int bx = blockIdx.x;
    int dir = bx >> 8;
    int t0 = (bx & 255) * 8;
    int tid = threadIdx.x;
#pragma unroll
    for (int i = 0; i < 8; i++) {
        xs[i][tid] = embed[(size_t)sent[t0 + i] * 256 + tid];
    }
    __syncthreads();
    const float* W = dir ? Wb : Wf;
    const float* bi = dir ? bihb : bihf;
    const float* bh = dir ? bhhb : bhhf;
    int r0 = tid * 4;
    unsigned long long acc2[8][4];
#pragma unroll
    for (int t = 0; t < 8; t++)
#pragma unroll
        for (int r = 0; r < 4; r++) acc2[t][r] = 0ull;

#pragma unroll 1
    for (int e = 0; e < 256; e += 4) {
        ulonglong2 w0 = *(const ulonglong2*)(W + (size_t)(r0 + 0) * 256 + e);
        ulonglong2 w1 = *(const ulonglong2*)(W + (size_t)(r0 + 1) * 256 + e);
        ulonglong2 w2 = *(const ulonglong2*)(W + (size_t)(r0 + 2) * 256 + e);
        ulonglong2 w3 = *(const ulonglong2*)(W + (size_t)(r0 + 3) * 256 + e);
#pragma unroll
        for (int t = 0; t < 8; t++) {
            ulonglong2 xv = *(const ulonglong2*)(&xs[t][e]);
            acc2[t][0] = fma2(w0.x, xv.x, acc2[t][0]);
            acc2[t][0] = fma2(w0.y, xv.y, acc2[t][0]);
            acc2[t][1] = fma2(w1.x, xv.x, acc2[t][1]);
            acc2[t][1] = fma2(w1.y, xv.y, acc2[t][1]);
            acc2[t][2] = fma2(w2.x, xv.x, acc2[t][2]);
            acc2[t][2] = fma2(w2.y, xv.y, acc2[t][2]);
            acc2[t][3] = fma2(w3.x, xv.x, acc2[t][3]);
            acc2[t][3] = fma2(w3.y, xv.y, acc2[t][3]);
        }
    }
    float bs[4];
#pragma unroll
    for (int r = 0; r < 4; r++) bs[r] = bi[r0 + r] + bh[r0 + r];
#pragma unroll
    for (int t = 0; t < 8; t++) {
        float4 o;
        float2 p0 = unpack2(acc2[t][0]);
        float2 p1 = unpack2(acc2[t][1]);
        float2 p2 = unpack2(acc2[t][2]);
        float2 p3 = unpack2(acc2[t][3]);
        o.x = p0.x + p0.y + bs[0];
        o.y = p1.x + p1.y + bs[1];
        o.z = p2.x + p2.y + bs[2];
        o.w = p3.x + p3.y + bs[3];
        *(float4*)(&g_pre[dir][t0 + t][r0]) = o;
    }
}

// ---------------- kernel B: LSTM recurrence (R10 WIN protocol, unchanged) ----------------
__global__ void __cluster_dims__(8, 1, 1) __launch_bounds__(256, 1)
lstm_kernel(const float* __restrict__ Whh_f, const float* __restrict__ Whh_b,
            const float* __restrict__ h0, const float* __restrict__ c0) {
    __shared__ __align__(16) float hbuf[2][256];
    __shared__ __align__(16) unsigned long long mbar[2];

    int tid = threadIdx.x;
    int dir = blockIdx.x >> 3;
    unsigned rank = ctarank();  // 0..7
    int wid = tid >> 5;
    int lane = tid & 31;
    int j = wid * 4 + (lane >> 3);        // 0..31 local hidden unit
    int gate = (lane >> 1) & 3;           // 0..3
    int seg = lane & 1;                   // K half
    int grow = gate * 256 + (int)rank * 32 + j;  // global gate row 0..1023
    int base = lane & 24;                 // lane of (j, gate0, seg0)

    const float* Whh = dir ? Whh_b : Whh_f;
    // this thread's 128 weights as 64 packed f32x2
    unsigned long long w2[64];
    {
        const ulonglong2* wp = (const ulonglong2*)(Whh + (size_t)grow * 256 + seg * 128);
#pragma unroll
        for (int i = 0; i < 32; i++) {
            ulonglong2 v = wp[i];
            w2[2 * i] = v.x;
            w2[2 * i + 1] = v.y;
        }
    }

    unsigned mb_local = smem_u32(&mbar[0]);
    if (tid == 0) {
        asm volatile("mbarrier.init.shared.b64 [%0], %1;" :: "r"(mb_local), "r"(1u) : "memory");
        asm volatile("mbarrier.init.shared.b64 [%0], %1;" :: "r"(mb_local + 8), "r"(1u) : "memory");
        asm volatile("fence.mbarrier_init.release.cluster;" ::: "memory");
        // pre-arm both parity slots: 1 arrive + expect 7*128 = 896 bytes each
        asm volatile("mbarrier.arrive.expect_tx.shared.b64 _, [%0], %1;" ::
                     "r"(mb_local), "r"(896u) : "memory");
        asm volatile("mbarrier.arrive.expect_tx.shared.b64 _, [%0], %1;" ::
                     "r"(mb_local + 8), "r"(896u) : "memory");
    }
    hbuf[0][tid] = h0[dir * 256 + tid];
    float c = 0.f;
    if ((lane & 7) == 0) c = c0[dir * 256 + (int)rank * 32 + j];

    // warp-parallel issuers: warp w (lane 0, w<7) -> peer (rank+1+w)&7
    unsigned my_dst_hb = 0, my_dst_mb = 0;
    unsigned src_slot = smem_u32(&hbuf[0][0]) + (unsigned)rank * 128u;  // my 128B slot
    if (lane == 0 && wid < 7) {
        unsigned peer = (rank + 1u + (unsigned)wid) & 7u;  // never == rank
        my_dst_hb = mapa_u32(src_slot, peer);
        my_dst_mb = mapa_u32(mb_local, peer);
    }
    const float* pre = &g_pre[dir][0][0];

    __syncthreads();
    CLUSTER_SYNC_();  // mbarrier inits/pre-arms + hbuf[0] visible cluster-wide

    float pv = 0.f;
    if (seg == 0) pv = pre[(size_t)(dir ? SEQT - 1 : 0) * 1024 + grow];
    int ph0 = 0, ph1 = 0;

#pragma unroll 1
    for (int s = 0; s < SEQT; s++) {
        int par = s & 1;
        // prefetch next step's input projection (hidden behind wait + matvec)
        float pv_next = 0.f;
        if (seg == 0 && s + 1 < SEQT) {
            int tn = dir ? (SEQT - 2 - s) : (s + 1);
            pv_next = pre[(size_t)tn * 1024 + grow];
        }
        if (s > 0) {
            if (par) {
                mbar_wait_cluster(mb_local + 8, ph1);
                ph1 ^= 1;
            } else {
                mbar_wait_cluster(mb_local, ph0);
                ph0 ^= 1;
            }
        }

        // half-row dot product (weights in registers, h broadcast from SMEM);
        // pv pre-seeded into accumulator a0 (seg1 lanes seed 0)
        const ulonglong2* hp = (const ulonglong2*)(&hbuf[par][seg * 128]);
        unsigned long long a0 = pack2f(pv, 0.f), a1 = 0ull, a2 = 0ull, a3 = 0ull;
#pragma unroll
        for (int i = 0; i < 32; i += 2) {
            ulonglong2 v0 = hp[i];
            ulonglong2 v1 = hp[i + 1];
            a0 = fma2(w2[2 * i + 0], v0.x, a0);
            a1 = fma2(w2[2 * i + 1], v0.y, a1);
            a2 = fma2(w2[2 * i + 2], v1.x, a2);
            a3 = fma2(w2[2 * i + 3], v1.y, a3);
        }
        a0 = add2(a0, a1);
        a2 = add2(a2, a3);
        a0 = add2(a0, a2);
        float2 fa = unpack2(a0);
        float sum = fa.x + fa.y;
        sum += __shfl_xor_sync(0xffffffffu, sum, 1);  // combine K halves (pv incl.)
        // single-MUFU activations: tanh for gate 2, sigmoid = 0.5+0.5*tanh(x/2)
        float av = (gate == 2) ? tanh_hw(sum) : sig_hw(sum);

        float gi = __shfl_sync(0xffffffffu, av, base + 0);
        float gf = __shfl_sync(0xffffffffu, av, base + 2);
        float gg = __shfl_sync(0xffffffffu, av, base + 4);
        float go = __shfl_sync(0xffffffffu, av, base + 6);

        float h = 0.f;
        if ((lane & 7) == 0) {
            c = gf * c + gi * gg;
            h = go * tanh_hw(c);
            hbuf[par ^ 1][(int)rank * 32 + j] = h;  // publish FIRST (copy source)
        }
        __syncthreads();  // publish h slot for next-step readers AND copy engine
        if (s + 1 < SEQT && lane == 0 && wid < 7) {
            asm volatile("fence.proxy.async.shared::cta;" ::: "memory");
            unsigned off = (unsigned)((par ^ 1) * 1024);
            bulk_dsmem(my_dst_hb + off, src_slot + off, 128u,
                       my_dst_mb + (unsigned)((par ^ 1) * 8));
        }
        // re-arm consumed slot for step s+2 — warp 7, off the wake path
        if (s > 0 && tid == 224) {
            asm volatile("mbarrier.arrive.expect_tx.shared.b64 _, [%0], %1;" ::
                         "r"(mb_local + (unsigned)(par * 8)), "r"(896u) : "memory");
        }
        if ((lane & 7) == 0) {  // off the critical path: drain to global
            int t = dir ? (SEQT - 1 - s) : s;
            g_hs[t][dir * 256 + (int)rank * 32 + j] = h;
        }
        pv = pv_next;
    }
    CLUSTER_SYNC_();  // no CTA exits while peers' copies may target its SMEM
}

// ---------------- kernel D: fused emissions + CRF chunk products ----------------
// 64 blocks x 384 threads. Phase 1: warp w (0..11) computes emissions for tag w
// over the chunk's 32 timesteps. Phase 2: serial log-semiring 32-product
// (threads 0..143, block-synced, __logf fast log).
__global__ void __launch_bounds__(384) crf_chunk_kernel(const float* __restrict__ W_out,
                                                        const float* __restrict__ b_out,
                                                        const float* __restrict__ trans) {
    __shared__ __align__(16) float Wc[NTAG][512];
    __shared__ float T[NTAG][NTAG];
    __shared__ float P[2][NTAG][NTAG + 1];
    __shared__ float em[32][NTAG];
    int tid = threadIdx.x;
    int wrp = tid >> 5, lane = tid & 31;
    int t0 = blockIdx.x * 32;

    // stage W_out (6144 floats) + transitions
    for (int idx = tid; idx < NTAG * 512; idx += 384) ((float*)Wc)[idx] = W_out[idx];
    if (tid < NTAG * NTAG) ((float*)T)[tid] = trans[tid];
    __syncthreads();

    // Phase 1: emissions. warp w -> tag w, loop over 32 timesteps.
    if (wrp < NTAG) {
        float bo = b_out[wrp];
        for (int i = 0; i < 32; i++) {
            const float* hrow = &g_hs[t0 + i][0];
            float a = 0.f;
#pragma unroll
            for (int k = 0; k < 16; k++) {
                int kk = lane + 32 * k;
                a = fmaf(__ldg(hrow + kk), Wc[wrp][kk], a);
            }
#pragma unroll
            for (int off = 16; off > 0; off >>= 1) a += __shfl_xor_sync(0xffffffffu, a, off);
            if (lane == 0) {
                float e = a + bo;
                em[i][wrp] = e;
                g_feats[t0 + i][wrp] = e;  // still needed by the gold score
            }
        }
    }
    __syncthreads();

    // Phase 2: serial log-semiring product over the 32 steps (threads 0..143)
    if (tid < NTAG * NTAG) {
        int n = tid / NTAG, p = tid - n * NTAG;
        P[0][n][p] = T[n][p] + em[0][n];
    }
    __syncthreads();
    int cur = 0;
#pragma unroll 1
    for (int s = 1; s < 32; s++) {
        if (tid < NTAG * NTAG) {
            int n = tid / NTAG, p = tid - n * NTAG;
            float m = -1e30f;
#pragma unroll
            for (int k = 0; k < NTAG; k++) m = fmaxf(m, T[n][k] + P[cur][k][p]);
            float sm = 0.f;
#pragma unroll
            for (int k = 0; k < NTAG; k++) sm += __expf(T[n][k] + P[cur][k][p] - m);
            P[cur ^ 1][n][p] = em[s][n] + m + __logf(sm);
        }
        __syncthreads();
        cur ^= 1;
    }
    if (tid < NTAG * NTAG) {
        int n = tid / NTAG, p = tid - n * NTAG;
        g_P[blockIdx.x][n][p] = P[cur][n][p];
    }
}

// ---------------- kernel E: final combine + gold score ----------------
// Serial 64-chunk combine with: double-buffered SMEM prefetch of the next
// chunk matrix (144-thread parallel LDG, off the serial chain) + __logf.
__global__ void __launch_bounds__(256) crf_final_kernel(const int* __restrict__ tags,
                                                        const float* __restrict__ trans,
                                                        float* __restrict__ out) {
    __shared__ float red[256];
    __shared__ float v[NTAG], nv[NTAG];
    __shared__ float Pm[2][NTAG][NTAG + 1];
    int tid = threadIdx.x;
    int n12 = tid / NTAG, p12 = tid - n12 * NTAG;  // valid for tid < 144
    float gs = 0.f;
    for (int t = tid; t < SEQT; t += 256) {
        int tg = tags[t];
        int pv = (t == 0) ? STARTT : tags[t - 1];
        gs += trans[tg * NTAG + pv] + g_feats[t][tg];
    }
    red[tid] = gs;
    if (tid < NTAG) v[tid] = (tid == STARTT) ? 0.f : NEGV;
    if (tid < NTAG * NTAG) Pm[0][n12][p12] = g_P[0][n12][p12];  // preload chunk 0
    __syncthreads();
    for (int off = 128; off > 0; off >>= 1) {
        if (tid < off) red[tid] += red[tid + off];
        __syncthreads();
    }
#pragma unroll 1
    for (int cidx = 0; cidx < SEQT / 32; cidx++) {
        int buf = cidx & 1;
        // prefetch next chunk matrix in parallel (hidden behind the combine)
        if (tid < NTAG * NTAG && cidx + 1 < SEQT / 32)
            Pm[buf ^ 1][n12][p12] = g_P[cidx + 1][n12][p12];
        if (tid < NTAG) {
            float m = -1e30f;
#pragma unroll
            for (int p = 0; p < NTAG; p++) m = fmaxf(m, Pm[buf][tid][p] + v[p]);
            float s = 0.f;
#pragma unroll
            for (int p = 0; p < NTAG; p++) s += __expf(Pm[buf][tid][p] + v[p] - m);
            nv[tid] = m + __logf(s);
        }
        __syncthreads();
        if (tid < NTAG) v[tid] = nv[tid];
        __syncthreads();
    }
    if (tid == 0) {
        float m = -1e30f;
#pragma unroll
        for (int n = 0; n < NTAG; n++) m = fmaxf(m, v[n] + trans[STOPT * NTAG + n]);
        float s = 0.f;
#pragma unroll
        for (int n = 0; n < NTAG; n++) s += __expf(v[n] + trans[STOPT * NTAG + n] - m);
        float fwd = m + __logf(s);
        float gold = red[0] + trans[STOPT * NTAG + tags[SEQT - 1]];
        out[0] = fwd - gold;
    }
}

// ---------------- launch ----------------
extern "C" void kernel_launch(void* const* d_in, const int* in_sizes, int n_in,
                              void* d_out, int out_size) {
    const int* sent = (const int*)d_in[0];
    const int* tags = (const int*)d_in[1];
    const float* embed = (const float*)d_in[2];
    const float* Wih_f = (const float*)d_in[3];
    const float* Whh_f = (const float*)d_in[4];
    const float* bih_f = (const float*)d_in[5];
    const float* bhh_f = (const float*)d_in[6];
    const float* Wih_b = (const float*)d_in[7];
    const float* Whh_b = (const float*)d_in[8];
    const float* bih_b = (const float*)d_in[9];
    const float* bhh_b = (const float*)d_in[10];
    const float* W_out = (const float*)d_in[11];
    const float* b_out = (const float*)d_in[12];
    const float* h0 = (const float*)d_in[13];
    const float* c0 = (const float*)d_in[14];
    const float* trans = (const float*)d_in[15];
    float* out = (float*)d_out;

    proj_kernel<<<512, 256>>>(sent, embed, Wih_f, bih_f, bhh_f, Wih_b, bih_b, bhh_b);
    lstm_kernel<<<16, 256>>>(Whh_f, Whh_b, h0, c0);
    crf_chunk_kernel<<<SEQT / 32, 384>>>(W_out, b_out, trans);
    crf_final_kernel<<<1, 256>>>(tags, trans, out);
}

// round 15
// speedup vs baseline: 1.0163x; 1.0163x over previous
#include <cuda_runtime.h>
#include <cstdint>
#include <cstddef>

#define SEQT 2048
#define NTAG 12
#define STARTT 10
#define STOPT 11
#define NEGV -10000.0f

// ---------------- scratch (device globals; no allocation) ----------------
__device__ float g_pre[2][SEQT][1024];      // 16 MB: input projections (i,f,g,o rows)
__device__ float g_hs[SEQT][512];           // 4 MB: [hf | hb] per timestep
__device__ float g_feats[SEQT][NTAG];
__device__ float g_P[SEQT / 32][NTAG][NTAG];
__device__ float g_P2[8][NTAG][NTAG];       // level-2 combined chunk matrices

// ---------------- helpers ----------------
__device__ __forceinline__ unsigned long long fma2(unsigned long long a, unsigned long long b,
                                                   unsigned long long c) {
    unsigned long long d;
    asm("fma.rn.f32x2 %0, %1, %2, %3;" : "=l"(d) : "l"(a), "l"(b), "l"(c));
    return d;
}
__device__ __forceinline__ unsigned long long add2(unsigned long long a, unsigned long long b) {
    unsigned long long d;
    asm("add.rn.f32x2 %0, %1, %2;" : "=l"(d) : "l"(a), "l"(b));
    return d;
}
__device__ __forceinline__ float2 unpack2(unsigned long long u) {
    float2 f;
    asm("mov.b64 {%0, %1}, %2;" : "=f"(f.x), "=f"(f.y) : "l"(u));
    return f;
}
__device__ __forceinline__ unsigned smem_u32(const void* p) {
    return (unsigned)__cvta_generic_to_shared(p);
}
__device__ __forceinline__ unsigned ctarank() {
    unsigned r;
    asm("mov.u32 %0, %%cluster_ctarank;" : "=r"(r));
    return r;
}
__device__ __forceinline__ unsigned mapa_u32(unsigned local_addr, unsigned rank) {
    unsigned r;
    asm("mapa.shared::cluster.u32 %0, %1, %2;" : "=r"(r) : "r"(local_addr), "r"(rank));
    return r;
}
// HW tanh (MUFU.TANH, single ~16cyc MUFU vs 2 dependent MUFUs for exp-based)
__device__ __forceinline__ float tanh_hw(float x) {
    float y;
    asm("tanh.approx.f32 %0, %1;" : "=f"(y) : "f"(x));
    return y;
}
__device__ __forceinline__ float sig_hw(float x) {
    return fmaf(0.5f, tanh_hw(0.5f * x), 0.5f);
}

#define CLUSTER_SYNC_()                                                \
    do {                                                               \
        asm volatile("barrier.cluster.arrive.aligned;" ::: "memory");  \
        asm volatile("barrier.cluster.wait.aligned;" ::: "memory");    \
    } while (0)

// cluster-scope acquire parity wait on a local-CTA mbarrier (proven R2/R7-R10)
__device__ __forceinline__ void mbar_wait_cluster(unsigned addr, int phase) {
    unsigned done;
    asm volatile(
        "{\n\t.reg .pred p;\n\t"
        "mbarrier.try_wait.parity.acquire.cluster.shared::cta.b64 p, [%1], %2;\n\t"
        "selp.b32 %0, 1, 0, p;\n\t}"
        : "=r"(done) : "r"(addr), "r"((unsigned)phase) : "memory");
    if (!done) {
        asm volatile(
            "{\n\t.reg .pred P1;\n\t"
            "WL_%=:\n\t"
            "mbarrier.try_wait.parity.acquire.cluster.shared::cta.b64 P1, [%0], %1, 0x989680;\n\t"
            "@P1 bra.uni WD_%=;\n\t"
            "bra.uni WL_%=;\n\t"
            "WD_%=:\n\t}"
            :: "r"(addr), "r"((unsigned)phase) : "memory");
    }
}

// DSMEM bulk copy: local smem -> peer smem, completion tx on the PEER's mbarrier.
__device__ __forceinline__ void bulk_dsmem(unsigned dst_cluster, unsigned src_cta,
                                           unsigned bytes, unsigned mbar_cluster) {
    asm volatile(
        "cp.async.bulk.shared::cluster.shared::cta.mbarrier::complete_tx::bytes "
        "[%0], [%1], %2, [%3];"
        :: "r"(dst_cluster), "r"(src_cta), "r"(bytes), "r"(mbar_cluster)
        : "memory");
}

// ---------------- kernel A: embedding gather + input projection ----------------
__global__ void __launch_bounds__(256) proj_kernel(
    const int* __restrict__ sent, const float* __restrict__ embed,
    const float* __restrict__ Wf, const float* __restrict__ bihf, const float* __restrict__ bhhf,
    const float* __restrict__ Wb, const float* __restrict__ bihb, const float* __restrict__ bhhb) {
    __shared__ __align__(16) float xs[8][256];
    int bx = blockIdx.x;
    int dir = bx >> 8;
    int t0 = (bx & 255) * 8;
    int tid = threadIdx.x;
#pragma unroll
    for (int i = 0; i < 8; i++) {
        xs[i][tid] = embed[(size_t)sent[t0 + i] * 256 + tid];
    }
    __syncthreads();
    const float* W = dir ? Wb : Wf;
    const float* bi = dir ? bihb : bihf;
    const float* bh = dir ? bhhb : bhhf;
    int r0 = tid * 4;
    unsigned long long acc2[8][4];
#pragma unroll
    for (int t = 0; t < 8; t++)
#pragma unroll
        for (int r = 0; r < 4; r++) acc2[t][r] = 0ull;

#pragma unroll 1
    for (int e = 0; e < 256; e += 4) {
        ulonglong2 w0 = *(const ulonglong2*)(W + (size_t)(r0 + 0) * 256 + e);
        ulonglong2 w1 = *(const ulonglong2*)(W + (size_t)(r0 + 1) * 256 + e);
        ulonglong2 w2 = *(const ulonglong2*)(W + (size_t)(r0 + 2) * 256 + e);
        ulonglong2 w3 = *(const ulonglong2*)(W + (size_t)(r0 + 3) * 256 + e);
#pragma unroll
        for (int t = 0; t < 8; t++) {
            ulonglong2 xv = *(const ulonglong2*)(&xs[t][e]);
            acc2[t][0] = fma2(w0.x, xv.x, acc2[t][0]);
            acc2[t][0] = fma2(w0.y, xv.y, acc2[t][0]);
            acc2[t][1] = fma2(w1.x, xv.x, acc2[t][1]);
            acc2[t][1] = fma2(w1.y, xv.y, acc2[t][1]);
            acc2[t][2] = fma2(w2.x, xv.x, acc2[t][2]);
            acc2[t][2] = fma2(w2.y, xv.y, acc2[t][2]);
            acc2[t][3] = fma2(w3.x, xv.x, acc2[t][3]);
            acc2[t][3] = fma2(w3.y, xv.y, acc2[t][3]);
        }
    }
    float bs[4];
#pragma unroll
    for (int r = 0; r < 4; r++) bs[r] = bi[r0 + r] + bh[r0 + r];
#pragma unroll
    for (int t = 0; t < 8; t++) {
        float4 o;
        float2 p0 = unpack2(acc2[t][0]);
        float2 p1 = unpack2(acc2[t][1]);
        float2 p2 = unpack2(acc2[t][2]);
        float2 p3 = unpack2(acc2[t][3]);
        o.x = p0.x + p0.y + bs[0];
        o.y = p1.x + p1.y + bs[1];
        o.z = p2.x + p2.y + bs[2];
        o.w = p3.x + p3.y + bs[3];
        *(float4*)(&g_pre[dir][t0 + t][r0]) = o;
    }
}

// ---------------- kernel B: LSTM recurrence (exact R10 WIN, 2013.3us) ----------------
__global__ void __cluster_dims__(8, 1, 1) __launch_bounds__(256, 1)
lstm_kernel(const float* __restrict__ Whh_f, const float* __restrict__ Whh_b,
            const float* __restrict__ h0, const float* __restrict__ c0) {
    __shared__ __align__(16) float hbuf[2][256];
    __shared__ __align__(16) unsigned long long mbar[2];

    int tid = threadIdx.x;
    int dir = blockIdx.x >> 3;
    unsigned rank = ctarank();  // 0..7
    int wid = tid >> 5;
    int lane = tid & 31;
    int j = wid * 4 + (lane >> 3);        // 0..31 local hidden unit
    int gate = (lane >> 1) & 3;           // 0..3
    int seg = lane & 1;                   // K half
    int grow = gate * 256 + (int)rank * 32 + j;  // global gate row 0..1023
    int base = lane & 24;                 // lane of (j, gate0, seg0)

    const float* Whh = dir ? Whh_b : Whh_f;
    // this thread's 128 weights as 64 packed f32x2
    unsigned long long w2[64];
    {
        const ulonglong2* wp = (const ulonglong2*)(Whh + (size_t)grow * 256 + seg * 128);
#pragma unroll
        for (int i = 0; i < 32; i++) {
            ulonglong2 v = wp[i];
            w2[2 * i] = v.x;
            w2[2 * i + 1] = v.y;
        }
    }

    unsigned mb_local = smem_u32(&mbar[0]);
    if (tid == 0) {
        asm volatile("mbarrier.init.shared.b64 [%0], %1;" :: "r"(mb_local), "r"(1u) : "memory");
        asm volatile("mbarrier.init.shared.b64 [%0], %1;" :: "r"(mb_local + 8), "r"(1u) : "memory");
        asm volatile("fence.mbarrier_init.release.cluster;" ::: "memory");
        // pre-arm both parity slots: 1 arrive + expect 7*128 = 896 bytes each
        asm volatile("mbarrier.arrive.expect_tx.shared.b64 _, [%0], %1;" ::
                     "r"(mb_local), "r"(896u) : "memory");
        asm volatile("mbarrier.arrive.expect_tx.shared.b64 _, [%0], %1;" ::
                     "r"(mb_local + 8), "r"(896u) : "memory");
    }
    hbuf[0][tid] = h0[dir * 256 + tid];
    float c = 0.f;
    if ((lane & 7) == 0) c = c0[dir * 256 + (int)rank * 32 + j];

    // warp-parallel issuers: warp w (lane 0, w<7) -> peer (rank+1+w)&7
    unsigned my_dst_hb = 0, my_dst_mb = 0;
    unsigned src_slot = smem_u32(&hbuf[0][0]) + (unsigned)rank * 128u;  // my 128B slot
    if (lane == 0 && wid < 7) {
        unsigned peer = (rank + 1u + (unsigned)wid) & 7u;  // never == rank
        my_dst_hb = mapa_u32(src_slot, peer);
        my_dst_mb = mapa_u32(mb_local, peer);
    }
    const float* pre = &g_pre[dir][0][0];

    __syncthreads();
    CLUSTER_SYNC_();  // mbarrier inits/pre-arms + hbuf[0] visible cluster-wide

    float pv = 0.f;
    if (seg == 0) pv = pre[(size_t)(dir ? SEQT - 1 : 0) * 1024 + grow];
    int ph0 = 0, ph1 = 0;

#pragma unroll 1
    for (int s = 0; s < SEQT; s++) {
        int par = s & 1;
        // prefetch next step's input projection (hidden behind wait + matvec)
        float pv_next = 0.f;
        if (seg == 0 && s + 1 < SEQT) {
            int tn = dir ? (SEQT - 2 - s) : (s + 1);
            pv_next = pre[(size_t)tn * 1024 + grow];
        }
        if (s > 0) {
            if (par) {
                mbar_wait_cluster(mb_local + 8, ph1);
                ph1 ^= 1;
            } else {
                mbar_wait_cluster(mb_local, ph0);
                ph0 ^= 1;
            }
        }

        // half-row dot product (weights in registers, h broadcast from SMEM)
        const ulonglong2* hp = (const ulonglong2*)(&hbuf[par][seg * 128]);
        unsigned long long a0 = 0ull, a1 = 0ull, a2 = 0ull, a3 = 0ull;
#pragma unroll
        for (int i = 0; i < 32; i += 2) {
            ulonglong2 v0 = hp[i];
            ulonglong2 v1 = hp[i + 1];
            a0 = fma2(w2[2 * i + 0], v0.x, a0);
            a1 = fma2(w2[2 * i + 1], v0.y, a1);
            a2 = fma2(w2[2 * i + 2], v1.x, a2);
            a3 = fma2(w2[2 * i + 3], v1.y, a3);
        }
        a0 = add2(a0, a1);
        a2 = add2(a2, a3);
        a0 = add2(a0, a2);
        float2 fa = unpack2(a0);
        float sum = fa.x + fa.y;
        sum += __shfl_xor_sync(0xffffffffu, sum, 1);  // combine K halves
        float g = sum + pv;                            // valid on seg0 lanes
        // single-MUFU activations: tanh for gate 2, sigmoid = 0.5+0.5*tanh(x/2)
        float av = (gate == 2) ? tanh_hw(g) : sig_hw(g);

        float gi = __shfl_sync(0xffffffffu, av, base + 0);
        float gf = __shfl_sync(0xffffffffu, av, base + 2);
        float gg = __shfl_sync(0xffffffffu, av, base + 4);
        float go = __shfl_sync(0xffffffffu, av, base + 6);

        float h = 0.f;
        if ((lane & 7) == 0) {
            c = gf * c + gi * gg;
            h = go * tanh_hw(c);
            hbuf[par ^ 1][(int)rank * 32 + j] = h;  // publish FIRST (copy source)
        }
        __syncthreads();  // publish h slot for next-step readers AND copy engine
        if (s + 1 < SEQT && lane == 0 && wid < 7) {
            asm volatile("fence.proxy.async.shared::cta;" ::: "memory");
            unsigned off = (unsigned)((par ^ 1) * 1024);
            bulk_dsmem(my_dst_hb + off, src_slot + off, 128u,
                       my_dst_mb + (unsigned)((par ^ 1) * 8));
        }
        // re-arm consumed slot for step s+2 — warp 7, off the wake path
        if (s > 0 && tid == 224) {
            asm volatile("mbarrier.arrive.expect_tx.shared.b64 _, [%0], %1;" ::
                         "r"(mb_local + (unsigned)(par * 8)), "r"(896u) : "memory");
        }
        if ((lane & 7) == 0) {  // off the critical path: drain to global
            int t = dir ? (SEQT - 1 - s) : s;
            g_hs[t][dir * 256 + (int)rank * 32 + j] = h;
        }
        pv = pv_next;
    }
    CLUSTER_SYNC_();  // no CTA exits while peers' copies may target its SMEM
}

// ---------------- kernel C: emissions (R10 version) ----------------
__global__ void __launch_bounds__(128) feats_kernel(const float* __restrict__ W_out,
                                                    const float* __restrict__ b_out) {
    int t = blockIdx.x;
    __shared__ __align__(16) float hs_s[512];
    int tid = threadIdx.x;
    ((float4*)hs_s)[tid] = ((const float4*)&g_hs[t][0])[tid];
    __syncthreads();
    int w = tid >> 5, lane = tid & 31;
    for (int tag = w; tag < NTAG; tag += 4) {
        float a = 0.f;
#pragma unroll
        for (int i = 0; i < 16; i++) {
            int k = lane + 32 * i;
            a = fmaf(hs_s[k], W_out[tag * 512 + k], a);
        }
#pragma unroll
        for (int off = 16; off > 0; off >>= 1) a += __shfl_xor_sync(0xffffffffu, a, off);
        if (lane == 0) g_feats[t][tag] = a + b_out[tag];
    }
}

// ---------------- kernel D: CRF chunked log-semiring products (R10 + __logf) ----------------
__global__ void __launch_bounds__(144) crf_chunk_kernel(const float* __restrict__ trans) {
    __shared__ float T[NTAG][NTAG];
    __shared__ float P[2][NTAG][NTAG + 1];
    __shared__ float em[32][NTAG];
    int tid = threadIdx.x;
    int n = tid / NTAG, p = tid - n * NTAG;
    int t0 = blockIdx.x * 32;
    T[n][p] = trans[tid];
    for (int idx = tid; idx < 32 * NTAG; idx += 144)
        em[idx / NTAG][idx % NTAG] = g_feats[t0 + idx / NTAG][idx % NTAG];
    __syncthreads();
    P[0][n][p] = T[n][p] + em[0][n];
    __syncthreads();
    int cur = 0;
#pragma unroll 1
    for (int s = 1; s < 32; s++) {
        float m = -1e30f;
#pragma unroll
        for (int k = 0; k < NTAG; k++) m = fmaxf(m, T[n][k] + P[cur][k][p]);
        float sm = 0.f;
#pragma unroll
        for (int k = 0; k < NTAG; k++) sm += __expf(T[n][k] + P[cur][k][p] - m);
        P[cur ^ 1][n][p] = em[s][n] + m + __logf(sm);
        __syncthreads();
        cur ^= 1;
    }
    g_P[blockIdx.x][n][p] = P[cur][n][p];
}

// ---------------- kernel D2: level-2 combine (NEW) ----------------
// 8 blocks x 144 threads. Block g computes Q_g = P_{8g+7} (x) ... (x) P_{8g}
// via 7 sequential full 12x12 log-matmuls, all 144 outputs in parallel.
__global__ void __launch_bounds__(144) crf_mid_kernel() {
    __shared__ float R[2][NTAG][NTAG + 1];
    __shared__ float A[NTAG][NTAG + 1];
    int tid = threadIdx.x;
    int n = tid / NTAG, p = tid - n * NTAG;
    int g = blockIdx.x;
    R[0][n][p] = g_P[g * 8][n][p];
    __syncthreads();
    int cur = 0;
#pragma unroll 1
    for (int i = 1; i < 8; i++) {
        A[n][p] = g_P[g * 8 + i][n][p];
        __syncthreads();
        float m = -1e30f;
#pragma unroll
        for (int k = 0; k < NTAG; k++) m = fmaxf(m, A[n][k] + R[cur][k][p]);
        float sm = 0.f;
#pragma unroll
        for (int k = 0; k < NTAG; k++) sm += __expf(A[n][k] + R[cur][k][p] - m);
        R[cur ^ 1][n][p] = m + __logf(sm);
        __syncthreads();
        cur ^= 1;
    }
    g_P2[g][n][p] = R[cur][n][p];
}

// ---------------- kernel E: final combine (8 matrices) + gold score ----------------
__global__ void __launch_bounds__(256) crf_final_kernel(const int* __restrict__ tags,
                                                        const float* __restrict__ trans,
                                                        float* __restrict__ out) {
    __shared__ float red[256];
    __shared__ float v[NTAG], nv[NTAG];
    __shared__ float Pm[8][NTAG][NTAG + 1];
    int tid = threadIdx.x;
    float gs = 0.f;
    for (int t = tid; t < SEQT; t += 256) {
        int tg = tags[t];
        int pv = (t == 0) ? STARTT : tags[t - 1];
        gs += trans[tg * NTAG + pv] + g_feats[t][tg];
    }
    red[tid] = gs;
    if (tid < NTAG) v[tid] = (tid == STARTT) ? 0.f : NEGV;
    // parallel preload of ALL 8 combined matrices (1152 floats, 256 threads)
    for (int idx = tid; idx < 8 * NTAG * NTAG; idx += 256) {
        int gg = idx / (NTAG * NTAG);
        int r = idx - gg * NTAG * NTAG;
        Pm[gg][r / NTAG][r % NTAG] = g_P2[gg][r / NTAG][r % NTAG];
    }
    __syncthreads();
    for (int off = 128; off > 0; off >>= 1) {
        if (tid < off) red[tid] += red[tid + off];
        __syncthreads();
    }
#pragma unroll 1
    for (int cidx = 0; cidx < 8; cidx++) {
        if (tid < NTAG) {
            float m = -1e30f;
#pragma unroll
            for (int p = 0; p < NTAG; p++) m = fmaxf(m, Pm[cidx][tid][p] + v[p]);
            float s = 0.f;
#pragma unroll
            for (int p = 0; p < NTAG; p++) s += __expf(Pm[cidx][tid][p] + v[p] - m);
            nv[tid] = m + __logf(s);
        }
        __syncthreads();
        if (tid < NTAG) v[tid] = nv[tid];
        __syncthreads();
    }
    if (tid == 0) {
        float m = -1e30f;
#pragma unroll
        for (int n = 0; n < NTAG; n++) m = fmaxf(m, v[n] + trans[STOPT * NTAG + n]);
        float s = 0.f;
#pragma unroll
        for (int n = 0; n < NTAG; n++) s += __expf(v[n] + trans[STOPT * NTAG + n] - m);
        float fwd = m + __logf(s);
        float gold = red[0] + trans[STOPT * NTAG + tags[SEQT - 1]];
        out[0] = fwd - gold;
    }
}

// ---------------- launch ----------------
extern "C" void kernel_launch(void* const* d_in, const int* in_sizes, int n_in,
                              void* d_out, int out_size) {
    const int* sent = (const int*)d_in[0];
    const int* tags = (const int*)d_in[1];
    const float* embed = (const float*)d_in[2];
    const float* Wih_f = (const float*)d_in[3];
    const float* Whh_f = (const float*)d_in[4];
    const float* bih_f = (const float*)d_in[5];
    const float* bhh_f = (const float*)d_in[6];
    const float* Wih_b = (const float*)d_in[7];
    const float* Whh_b = (const float*)d_in[8];
    const float* bih_b = (const float*)d_in[9];
    const float* bhh_b = (const float*)d_in[10];
    const float* W_out = (const float*)d_in[11];
    const float* b_out = (const float*)d_in[12];
    const float* h0 = (const float*)d_in[13];
    const float* c0 = (const float*)d_in[14];
    const float* trans = (const float*)d_in[15];
    float* out = (float*)d_out;

    proj_kernel<<<512, 256>>>(sent, embed, Wih_f, bih_f, bhh_f, Wih_b, bih_b, bhh_b);
    lstm_kernel<<<16, 256>>>(Whh_f, Whh_b, h0, c0);
    feats_kernel<<<SEQT, 128>>>(W_out, b_out);
    crf_chunk_kernel<<<SEQT / 32, 144>>>(trans);
    crf_mid_kernel<<<8, 144>>>();
    crf_final_kernel<<<1, 256>>>(tags, trans, out);
}

// round 16
// speedup vs baseline: 1.0435x; 1.0268x over previous
#include <cuda_runtime.h>
#include <cstdint>
#include <cstddef>

#define SEQT 2048
#define NTAG 12
#define STARTT 10
#define STOPT 11
#define NEGV -10000.0f
#define CHUNK 16
#define NCHUNK (SEQT / CHUNK)   // 128
#define NMID 8
#define PERMID (NCHUNK / NMID)  // 16

// ---------------- scratch (device globals; no allocation) ----------------
__device__ float g_pre[2][SEQT][1024];      // 16 MB: input projections (i,f,g,o rows)
__device__ float g_hs[SEQT][512];           // 4 MB: [hf | hb] per timestep
__device__ float g_feats[SEQT][NTAG];
__device__ float g_P[NCHUNK][NTAG][NTAG];
__device__ float g_P2[NMID][NTAG][NTAG];    // level-2 combined chunk matrices

// ---------------- helpers ----------------
__device__ __forceinline__ unsigned long long fma2(unsigned long long a, unsigned long long b,
                                                   unsigned long long c) {
    unsigned long long d;
    asm("fma.rn.f32x2 %0, %1, %2, %3;" : "=l"(d) : "l"(a), "l"(b), "l"(c));
    return d;
}
__device__ __forceinline__ unsigned long long add2(unsigned long long a, unsigned long long b) {
    unsigned long long d;
    asm("add.rn.f32x2 %0, %1, %2;" : "=l"(d) : "l"(a), "l"(b));
    return d;
}
__device__ __forceinline__ float2 unpack2(unsigned long long u) {
    float2 f;
    asm("mov.b64 {%0, %1}, %2;" : "=f"(f.x), "=f"(f.y) : "l"(u));
    return f;
}
__device__ __forceinline__ unsigned smem_u32(const void* p) {
    return (unsigned)__cvta_generic_to_shared(p);
}
__device__ __forceinline__ unsigned ctarank() {
    unsigned r;
    asm("mov.u32 %0, %%cluster_ctarank;" : "=r"(r));
    return r;
}
__device__ __forceinline__ unsigned mapa_u32(unsigned local_addr, unsigned rank) {
    unsigned r;
    asm("mapa.shared::cluster.u32 %0, %1, %2;" : "=r"(r) : "r"(local_addr), "r"(rank));
    return r;
}
// HW tanh (MUFU.TANH, single ~16cyc MUFU vs 2 dependent MUFUs for exp-based)
__device__ __forceinline__ float tanh_hw(float x) {
    float y;
    asm("tanh.approx.f32 %0, %1;" : "=f"(y) : "f"(x));
    return y;
}
__device__ __forceinline__ float sig_hw(float x) {
    return fmaf(0.5f, tanh_hw(0.5f * x), 0.5f);
}

#define CLUSTER_SYNC_()                                                \
    do {                                                               \
        asm volatile("barrier.cluster.arrive.aligned;" ::: "memory");  \
        asm volatile("barrier.cluster.wait.aligned;" ::: "memory");    \
    } while (0)

// cluster-scope acquire parity wait on a local-CTA mbarrier (proven R2/R7-R10)
__device__ __forceinline__ void mbar_wait_cluster(unsigned addr, int phase) {
    unsigned done;
    asm volatile(
        "{\n\t.reg .pred p;\n\t"
        "mbarrier.try_wait.parity.acquire.cluster.shared::cta.b64 p, [%1], %2;\n\t"
        "selp.b32 %0, 1, 0, p;\n\t}"
        : "=r"(done) : "r"(addr), "r"((unsigned)phase) : "memory");
    if (!done) {
        asm volatile(
            "{\n\t.reg .pred P1;\n\t"
            "WL_%=:\n\t"
            "mbarrier.try_wait.parity.acquire.cluster.shared::cta.b64 P1, [%0], %1, 0x989680;\n\t"
            "@P1 bra.uni WD_%=;\n\t"
            "bra.uni WL_%=;\n\t"
            "WD_%=:\n\t}"
            :: "r"(addr), "r"((unsigned)phase) : "memory");
    }
}

// DSMEM bulk copy: local smem -> peer smem, completion tx on the PEER's mbarrier.
__device__ __forceinline__ void bulk_dsmem(unsigned dst_cluster, unsigned src_cta,
                                           unsigned bytes, unsigned mbar_cluster) {
    asm volatile(
        "cp.async.bulk.shared::cluster.shared::cta.mbarrier::complete_tx::bytes "
        "[%0], [%1], %2, [%3];"
        :: "r"(dst_cluster), "r"(src_cta), "r"(bytes), "r"(mbar_cluster)
        : "memory");
}

// ---------------- kernel A: embedding gather + input projection ----------------
// 16 timesteps/block (halves W L2 traffic vs 8t), 512 threads x 2 rows each.
__global__ void __launch_bounds__(512) proj_kernel(
    const int* __restrict__ sent, const float* __restrict__ embed,
    const float* __restrict__ Wf, const float* __restrict__ bihf, const float* __restrict__ bhhf,
    const float* __restrict__ Wb, const float* __restrict__ bihb, const float* __restrict__ bhhb) {
    __shared__ __align__(16) float xs[16][256];
    int bx = blockIdx.x;
    int dir = bx >> 7;
    int t0 = (bx & 127) * 16;
    int tid = threadIdx.x;
#pragma unroll
    for (int k = 0; k < 8; k++) {
        int idx = k * 512 + tid;            // 0..4095
        int i = idx >> 8, e = idx & 255;
        xs[i][e] = embed[(size_t)sent[t0 + i] * 256 + e];
    }
    __syncthreads();
    const float* W = dir ? Wb : Wf;
    const float* bi = dir ? bihb : bihf;
    const float* bh = dir ? bhhb : bhhf;
    int r0 = tid * 2;
    unsigned long long acc2[16][2];
#pragma unroll
    for (int t = 0; t < 16; t++) {
        acc2[t][0] = 0ull;
        acc2[t][1] = 0ull;
    }

#pragma unroll 1
    for (int e = 0; e < 256; e += 4) {
        ulonglong2 w0 = *(const ulonglong2*)(W + (size_t)(r0 + 0) * 256 + e);
        ulonglong2 w1 = *(const ulonglong2*)(W + (size_t)(r0 + 1) * 256 + e);
#pragma unroll
        for (int t = 0; t < 16; t++) {
            ulonglong2 xv = *(const ulonglong2*)(&xs[t][e]);
            acc2[t][0] = fma2(w0.x, xv.x, acc2[t][0]);
            acc2[t][0] = fma2(w0.y, xv.y, acc2[t][0]);
            acc2[t][1] = fma2(w1.x, xv.x, acc2[t][1]);
            acc2[t][1] = fma2(w1.y, xv.y, acc2[t][1]);
        }
    }
    float bs0 = bi[r0] + bh[r0];
    float bs1 = bi[r0 + 1] + bh[r0 + 1];
#pragma unroll
    for (int t = 0; t < 16; t++) {
        float2 o;
        float2 p0 = unpack2(acc2[t][0]);
        float2 p1 = unpack2(acc2[t][1]);
        o.x = p0.x + p0.y + bs0;
        o.y = p1.x + p1.y + bs1;
        *(float2*)(&g_pre[dir][t0 + t][r0]) = o;
    }
}

// ---------------- kernel B: LSTM recurrence (exact R10 WIN protocol) ----------------
__global__ void __cluster_dims__(8, 1, 1) __launch_bounds__(256, 1)
lstm_kernel(const float* __restrict__ Whh_f, const float* __restrict__ Whh_b,
            const float* __restrict__ h0, const float* __restrict__ c0) {
    __shared__ __align__(16) float hbuf[2][256];
    __shared__ __align__(16) unsigned long long mbar[2];

    int tid = threadIdx.x;
    int dir = blockIdx.x >> 3;
    unsigned rank = ctarank();  // 0..7
    int wid = tid >> 5;
    int lane = tid & 31;
    int j = wid * 4 + (lane >> 3);        // 0..31 local hidden unit
    int gate = (lane >> 1) & 3;           // 0..3
    int seg = lane & 1;                   // K half
    int grow = gate * 256 + (int)rank * 32 + j;  // global gate row 0..1023
    int base = lane & 24;                 // lane of (j, gate0, seg0)

    const float* Whh = dir ? Whh_b : Whh_f;
    // this thread's 128 weights as 64 packed f32x2
    unsigned long long w2[64];
    {
        const ulonglong2* wp = (const ulonglong2*)(Whh + (size_t)grow * 256 + seg * 128);
#pragma unroll
        for (int i = 0; i < 32; i++) {
            ulonglong2 v = wp[i];
            w2[2 * i] = v.x;
            w2[2 * i + 1] = v.y;
        }
    }

    unsigned mb_local = smem_u32(&mbar[0]);
    if (tid == 0) {
        asm volatile("mbarrier.init.shared.b64 [%0], %1;" :: "r"(mb_local), "r"(1u) : "memory");
        asm volatile("mbarrier.init.shared.b64 [%0], %1;" :: "r"(mb_local + 8), "r"(1u) : "memory");
        asm volatile("fence.mbarrier_init.release.cluster;" ::: "memory");
        // pre-arm both parity slots: 1 arrive + expect 7*128 = 896 bytes each
        asm volatile("mbarrier.arrive.expect_tx.shared.b64 _, [%0], %1;" ::
                     "r"(mb_local), "r"(896u) : "memory");
        asm volatile("mbarrier.arrive.expect_tx.shared.b64 _, [%0], %1;" ::
                     "r"(mb_local + 8), "r"(896u) : "memory");
    }
    hbuf[0][tid] = h0[dir * 256 + tid];
    float c = 0.f;
    if ((lane & 7) == 0) c = c0[dir * 256 + (int)rank * 32 + j];

    // warp-parallel issuers: warp w (lane 0, w<7) -> peer (rank+1+w)&7
    unsigned my_dst_hb = 0, my_dst_mb = 0;
    unsigned src_slot = smem_u32(&hbuf[0][0]) + (unsigned)rank * 128u;  // my 128B slot
    if (lane == 0 && wid < 7) {
        unsigned peer = (rank + 1u + (unsigned)wid) & 7u;  // never == rank
        my_dst_hb = mapa_u32(src_slot, peer);
        my_dst_mb = mapa_u32(mb_local, peer);
    }
    const float* pre = &g_pre[dir][0][0];

    __syncthreads();
    CLUSTER_SYNC_();  // mbarrier inits/pre-arms + hbuf[0] visible cluster-wide

    float pv = 0.f;
    if (seg == 0) pv = pre[(size_t)(dir ? SEQT - 1 : 0) * 1024 + grow];
    int ph0 = 0, ph1 = 0;

#pragma unroll 1
    for (int s = 0; s < SEQT; s++) {
        int par = s & 1;
        // prefetch next step's input projection (hidden behind wait + matvec)
        float pv_next = 0.f;
        if (seg == 0 && s + 1 < SEQT) {
            int tn = dir ? (SEQT - 2 - s) : (s + 1);
            pv_next = pre[(size_t)tn * 1024 + grow];
        }
        if (s > 0) {
            if (par) {
                mbar_wait_cluster(mb_local + 8, ph1);
                ph1 ^= 1;
            } else {
                mbar_wait_cluster(mb_local, ph0);
                ph0 ^= 1;
            }
        }

        // half-row dot product (weights in registers, h broadcast from SMEM)
        const ulonglong2* hp = (const ulonglong2*)(&hbuf[par][seg * 128]);
        unsigned long long a0 = 0ull, a1 = 0ull, a2 = 0ull, a3 = 0ull;
#pragma unroll
        for (int i = 0; i < 32; i += 2) {
            ulonglong2 v0 = hp[i];
            ulonglong2 v1 = hp[i + 1];
            a0 = fma2(w2[2 * i + 0], v0.x, a0);
            a1 = fma2(w2[2 * i + 1], v0.y, a1);
            a2 = fma2(w2[2 * i + 2], v1.x, a2);
            a3 = fma2(w2[2 * i + 3], v1.y, a3);
        }
        a0 = add2(a0, a1);
        a2 = add2(a2, a3);
        a0 = add2(a0, a2);
        float2 fa = unpack2(a0);
        float sum = fa.x + fa.y;
        sum += __shfl_xor_sync(0xffffffffu, sum, 1);  // combine K halves
        float g = sum + pv;                            // valid on seg0 lanes
        // single-MUFU activations: tanh for gate 2, sigmoid = 0.5+0.5*tanh(x/2)
        float av = (gate == 2) ? tanh_hw(g) : sig_hw(g);

        float gi = __shfl_sync(0xffffffffu, av, base + 0);
        float gf = __shfl_sync(0xffffffffu, av, base + 2);
        float gg = __shfl_sync(0xffffffffu, av, base + 4);
        float go = __shfl_sync(0xffffffffu, av, base + 6);

        float h = 0.f;
        if ((lane & 7) == 0) {
            c = gf * c + gi * gg;
            h = go * tanh_hw(c);
            hbuf[par ^ 1][(int)rank * 32 + j] = h;  // publish FIRST (copy source)
        }
        __syncthreads();  // publish h slot for next-step readers AND copy engine
        if (s + 1 < SEQT && lane == 0 && wid < 7) {
            asm volatile("fence.proxy.async.shared::cta;" ::: "memory");
            unsigned off = (unsigned)((par ^ 1) * 1024);
            bulk_dsmem(my_dst_hb + off, src_slot + off, 128u,
                       my_dst_mb + (unsigned)((par ^ 1) * 8));
        }
        // re-arm consumed slot for step s+2 — warp 7, off the wake path
        if (s > 0 && tid == 224) {
            asm volatile("mbarrier.arrive.expect_tx.shared.b64 _, [%0], %1;" ::
                         "r"(mb_local + (unsigned)(par * 8)), "r"(896u) : "memory");
        }
        if ((lane & 7) == 0) {  // off the critical path: drain to global
            int t = dir ? (SEQT - 1 - s) : s;
            g_hs[t][dir * 256 + (int)rank * 32 + j] = h;
        }
        pv = pv_next;
    }
    CLUSTER_SYNC_();  // no CTA exits while peers' copies may target its SMEM
}

// ---------------- kernel C: emissions (R10 version) ----------------
__global__ void __launch_bounds__(128) feats_kernel(const float* __restrict__ W_out,
                                                    const float* __restrict__ b_out) {
    int t = blockIdx.x;
    __shared__ __align__(16) float hs_s[512];
    int tid = threadIdx.x;
    ((float4*)hs_s)[tid] = ((const float4*)&g_hs[t][0])[tid];
    __syncthreads();
    int w = tid >> 5, lane = tid & 31;
    for (int tag = w; tag < NTAG; tag += 4) {
        float a = 0.f;
#pragma unroll
        for (int i = 0; i < 16; i++) {
            int k = lane + 32 * i;
            a = fmaf(hs_s[k], W_out[tag * 512 + k], a);
        }
#pragma unroll
        for (int off = 16; off > 0; off >>= 1) a += __shfl_xor_sync(0xffffffffu, a, off);
        if (lane == 0) g_feats[t][tag] = a + b_out[tag];
    }
}

// ---------------- kernel D: CRF chunked log-semiring products (16-step chunks) ----------------
__global__ void __launch_bounds__(144) crf_chunk_kernel(const float* __restrict__ trans) {
    __shared__ float T[NTAG][NTAG];
    __shared__ float P[2][NTAG][NTAG + 1];
    __shared__ float em[CHUNK][NTAG];
    int tid = threadIdx.x;
    int n = tid / NTAG, p = tid - n * NTAG;
    int t0 = blockIdx.x * CHUNK;
    T[n][p] = trans[tid];
    for (int idx = tid; idx < CHUNK * NTAG; idx += 144)
        em[idx / NTAG][idx % NTAG] = g_feats[t0 + idx / NTAG][idx % NTAG];
    __syncthreads();
    P[0][n][p] = T[n][p] + em[0][n];
    __syncthreads();
    int cur = 0;
#pragma unroll 1
    for (int s = 1; s < CHUNK; s++) {
        float m = -1e30f;
#pragma unroll
        for (int k = 0; k < NTAG; k++) m = fmaxf(m, T[n][k] + P[cur][k][p]);
        float sm = 0.f;
#pragma unroll
        for (int k = 0; k < NTAG; k++) sm += __expf(T[n][k] + P[cur][k][p] - m);
        P[cur ^ 1][n][p] = em[s][n] + m + __logf(sm);
        __syncthreads();
        cur ^= 1;
    }
    g_P[blockIdx.x][n][p] = P[cur][n][p];
}

// ---------------- kernel D2: level-2 combine ----------------
// 8 blocks x 144 threads. Block g computes Q_g = P_{16g+15} (x) ... (x) P_{16g}
// via 15 sequential full 12x12 log-matmuls, all 144 outputs in parallel.
__global__ void __launch_bounds__(144) crf_mid_kernel() {
    __shared__ float R[2][NTAG][NTAG + 1];
    __shared__ float A[NTAG][NTAG + 1];
    int tid = threadIdx.x;
    int n = tid / NTAG, p = tid - n * NTAG;
    int g = blockIdx.x;
    R[0][n][p] = g_P[g * PERMID][n][p];
    __syncthreads();
    int cur = 0;
#pragma unroll 1
    for (int i = 1; i < PERMID; i++) {
        A[n][p] = g_P[g * PERMID + i][n][p];
        __syncthreads();
        float m = -1e30f;
#pragma unroll
        for (int k = 0; k < NTAG; k++) m = fmaxf(m, A[n][k] + R[cur][k][p]);
        float sm = 0.f;
#pragma unroll
        for (int k = 0; k < NTAG; k++) sm += __expf(A[n][k] + R[cur][k][p] - m);
        R[cur ^ 1][n][p] = m + __logf(sm);
        __syncthreads();
        cur ^= 1;
    }
    g_P2[g][n][p] = R[cur][n][p];
}

// ---------------- kernel E: final combine (8 matrices) + gold score ----------------
__global__ void __launch_bounds__(256) crf_final_kernel(const int* __restrict__ tags,
                                                        const float* __restrict__ trans,
                                                        float* __restrict__ out) {
    __shared__ float red[256];
    __shared__ float v[NTAG], nv[NTAG];
    __shared__ float Pm[NMID][NTAG][NTAG + 1];
    int tid = threadIdx.x;
    float gs = 0.f;
    for (int t = tid; t < SEQT; t += 256) {
        int tg = tags[t];
        int pv = (t == 0) ? STARTT : tags[t - 1];
        gs += trans[tg * NTAG + pv] + g_feats[t][tg];
    }
    red[tid] = gs;
    if (tid < NTAG) v[tid] = (tid == STARTT) ? 0.f : NEGV;
    // parallel preload of ALL 8 combined matrices (1152 floats, 256 threads)
    for (int idx = tid; idx < NMID * NTAG * NTAG; idx += 256) {
        int gg = idx / (NTAG * NTAG);
        int r = idx - gg * NTAG * NTAG;
        Pm[gg][r / NTAG][r % NTAG] = g_P2[gg][r / NTAG][r % NTAG];
    }
    __syncthreads();
    for (int off = 128; off > 0; off >>= 1) {
        if (tid < off) red[tid] += red[tid + off];
        __syncthreads();
    }
#pragma unroll 1
    for (int cidx = 0; cidx < NMID; cidx++) {
        if (tid < NTAG) {
            float m = -1e30f;
#pragma unroll
            for (int p = 0; p < NTAG; p++) m = fmaxf(m, Pm[cidx][tid][p] + v[p]);
            float s = 0.f;
#pragma unroll
            for (int p = 0; p < NTAG; p++) s += __expf(Pm[cidx][tid][p] + v[p] - m);
            nv[tid] = m + __logf(s);
        }
        __syncthreads();
        if (tid < NTAG) v[tid] = nv[tid];
        __syncthreads();
    }
    if (tid == 0) {
        float m = -1e30f;
#pragma unroll
        for (int n = 0; n < NTAG; n++) m = fmaxf(m, v[n] + trans[STOPT * NTAG + n]);
        float s = 0.f;
#pragma unroll
        for (int n = 0; n < NTAG; n++) s += __expf(v[n] + trans[STOPT * NTAG + n] - m);
        float fwd = m + __logf(s);
        float gold = red[0] + trans[STOPT * NTAG + tags[SEQT - 1]];
        out[0] = fwd - gold;
    }
}

// ---------------- launch ----------------
extern "C" void kernel_launch(void* const* d_in, const int* in_sizes, int n_in,
                              void* d_out, int out_size) {
    const int* sent = (const int*)d_in[0];
    const int* tags = (const int*)d_in[1];
    const float* embed = (const float*)d_in[2];
    const float* Wih_f = (const float*)d_in[3];
    const float* Whh_f = (const float*)d_in[4];
    const float* bih_f = (const float*)d_in[5];
    const float* bhh_f = (const float*)d_in[6];
    const float* Wih_b = (const float*)d_in[7];
    const float* Whh_b = (const float*)d_in[8];
    const float* bih_b = (const float*)d_in[9];
    const float* bhh_b = (const float*)d_in[10];
    const float* W_out = (const float*)d_in[11];
    const float* b_out = (const float*)d_in[12];
    const float* h0 = (const float*)d_in[13];
    const float* c0 = (const float*)d_in[14];
    const float* trans = (const float*)d_in[15];
    float* out = (float*)d_out;

    proj_kernel<<<256, 512>>>(sent, embed, Wih_f, bih_f, bhh_f, Wih_b, bih_b, bhh_b);
    lstm_kernel<<<16, 256>>>(Whh_f, Whh_b, h0, c0);
    feats_kernel<<<SEQT, 128>>>(W_out, b_out);
    crf_chunk_kernel<<<NCHUNK, 144>>>(trans);
    crf_mid_kernel<<<NMID, 144>>>();
    crf_final_kernel<<<1, 256>>>(tags, trans, out);
}